// round 11
// baseline (speedup 1.0000x reference)
#include <cuda_runtime.h>
#include <cuda_bf16.h>
#include <math.h>
#include <stdint.h>

#define BB 32
#define NL 512
#define INDIM 1024
#define MEMD 1024

typedef __nv_bfloat16 bf16;

// ---------------- static scratch (no runtime allocation allowed) -------------
__device__ __align__(256) float g_c0[BB * NL * MEMD];
__device__ __align__(256) float g_c1[(BB * NL / 2) * MEMD];
__device__ __align__(256) bf16 g_h0hi[BB * NL * MEMD];
__device__ __align__(256) bf16 g_h0lo[BB * NL * MEMD];
__device__ __align__(256) bf16 g_h1hi[(BB * NL / 2) * MEMD];
__device__ __align__(256) bf16 g_h1lo[(BB * NL / 2) * MEMD];
__device__ __align__(256) bf16 g_xhi[(size_t)BB * NL * INDIM];
__device__ __align__(256) bf16 g_xlo[(size_t)BB * NL * INDIM];
__device__ __align__(256) bf16 g_wxhi[(size_t)3 * MEMD * INDIM];
__device__ __align__(256) bf16 g_wxlo[(size_t)3 * MEMD * INDIM];
__device__ __align__(256) bf16 g_wchi[(size_t)5 * MEMD * 2 * MEMD];
__device__ __align__(256) bf16 g_wclo[(size_t)5 * MEMD * 2 * MEMD];
__device__ __align__(256) float g_scr[(size_t)BB * NL * 3 * MEMD];

// ---------------- fused fp32 -> bf16 hi/lo split (4 segments, 1 launch) ------
__global__ void split_all(const float* __restrict__ s0, bf16* h0, bf16* l0, int n0,
                          const float* __restrict__ s1, bf16* h1, bf16* l1, int n1,
                          const float* __restrict__ s2, bf16* h2, bf16* l2, int n2,
                          const float* __restrict__ s3, bf16* h3, bf16* l3, int n3) {
    int i = blockIdx.x * blockDim.x + threadIdx.x;
    const float* s;
    bf16 *hi, *lo;
    int j = i;
    if (j < n0) { s = s0; hi = h0; lo = l0; }
    else {
        j -= n0;
        if (j < n1) { s = s1; hi = h1; lo = l1; }
        else {
            j -= n1;
            if (j < n2) { s = s2; hi = h2; lo = l2; }
            else {
                j -= n2;
                if (j >= n3) return;
                s = s3; hi = h3; lo = l3;
            }
        }
    }
    float4 v = ((const float4*)s)[j];
    bf16 a0 = __float2bfloat16(v.x), a1 = __float2bfloat16(v.y);
    bf16 a2 = __float2bfloat16(v.z), a3 = __float2bfloat16(v.w);
    ((__nv_bfloat162*)hi)[j * 2]     = __nv_bfloat162(a0, a1);
    ((__nv_bfloat162*)hi)[j * 2 + 1] = __nv_bfloat162(a2, a3);
    ((__nv_bfloat162*)lo)[j * 2] = __nv_bfloat162(
        __float2bfloat16(v.x - __bfloat162float(a0)),
        __float2bfloat16(v.y - __bfloat162float(a1)));
    ((__nv_bfloat162*)lo)[j * 2 + 1] = __nv_bfloat162(
        __float2bfloat16(v.z - __bfloat162float(a2)),
        __float2bfloat16(v.w - __bfloat162float(a3)));
}

// ============================================================================
// split-bf16 GEMM: C[M,N] = (Ahi+Alo)[M,K] * (Whi+Wlo)[N,K]^T  (K-major)
// BM=BN=128, BK=32. 8 warps (2x4): warp tile 64x32 = 4x4 m16n8k16 x 3 splits.
// XOR-swizzled 64B smem rows; 3-stage cp.async; one __syncthreads per chunk.
// mt-pair interleaving (chain dist 8) + B-fragment double buffer across ks
// (ks=1 B loads issued under ks=0's second MMA pair). Prefetch mid-compute.
// gridDim.z = deterministic K-slices writing disjoint partial outputs.
// ============================================================================
#define BM 128
#define BN 128
#define BK 32
#define PLANE_B 8192                 // 128 rows * 64B
#define STAGE_B (4 * PLANE_B)        // Ahi,Alo,Whi,Wlo
#define NSTG 3
#define SMEM_DYN (NSTG * STAGE_B + 128)

static __device__ __forceinline__ uint32_t smem_u32(const void* p) {
    uint32_t a;
    asm("{ .reg .u64 t; cvta.to.shared.u64 t, %1; cvt.u32.u64 %0, t; }"
        : "=r"(a) : "l"(p));
    return a;
}

#define LDM4(r0, r1, r2, r3, addr)                                            \
    asm volatile("ldmatrix.sync.aligned.m8n8.x4.shared.b16 {%0,%1,%2,%3}, [%4];" \
                 : "=r"(r0), "=r"(r1), "=r"(r2), "=r"(r3) : "r"(addr))

#define MMA_BF16(d, a, b)                                                     \
    asm volatile("mma.sync.aligned.m16n8k16.row.col.f32.bf16.bf16.f32 "       \
                 "{%0,%1,%2,%3},{%4,%5,%6,%7},{%8,%9},{%0,%1,%2,%3};"         \
                 : "+f"(d[0]), "+f"(d[1]), "+f"(d[2]), "+f"(d[3])             \
                 : "r"(a[0]), "r"(a[1]), "r"(a[2]), "r"(a[3]),                \
                   "r"(b[0]), "r"(b[1]))

static __device__ __forceinline__ void load_stage(
    const bf16* __restrict__ Ahi, const bf16* __restrict__ Alo,
    const bf16* __restrict__ Whi, const bf16* __restrict__ Wlo,
    int M, int K, int bm, int bn, int k0, uint32_t sbase, int tid) {
#pragma unroll
    for (int i = 0; i < 8; i++) {
        int l = tid + 256 * i;          // 0..2047
        int plane = l >> 9;             // 0:Ahi 1:Alo 2:Whi 3:Wlo
        int c = l & 511;
        int row = c >> 2;
        int ch = c & 3;
        int sc = ch ^ ((row >> 1) & 3);          // swizzled 16B chunk
        uint32_t dst = sbase + plane * PLANE_B + row * 64 + sc * 16;
        if (plane < 2) {
            const bf16* base = plane ? Alo : Ahi;
            int gr = bm + row;
            int ok = gr < M;
            const bf16* g = base + (size_t)(ok ? gr : 0) * K + k0 + ch * 8;
            int sz = ok ? 16 : 0;
            asm volatile("cp.async.cg.shared.global [%0], [%1], 16, %2;\n"
                         :: "r"(dst), "l"(g), "r"(sz));
        } else {
            const bf16* base = (plane == 2) ? Whi : Wlo;
            const bf16* g = base + (size_t)(bn + row) * K + k0 + ch * 8;
            asm volatile("cp.async.cg.shared.global [%0], [%1], 16;\n"
                         :: "r"(dst), "l"(g));
        }
    }
}

__global__ __launch_bounds__(256, 2)
void gemm_split(const bf16* __restrict__ Ahi, const bf16* __restrict__ Alo,
                const bf16* __restrict__ Whi, const bf16* __restrict__ Wlo,
                float* __restrict__ C, int M, int N, int K, int kcps) {
    extern __shared__ __align__(128) char smem_raw[];
    uint32_t sbase = smem_u32(smem_raw);
    sbase = (sbase + 127u) & ~127u;

    const int tid = threadIdx.x;
    const int wid = tid >> 5;
    const int lane = tid & 31;
    const int warp_m = wid >> 2;
    const int warp_n = wid & 3;
    const int bm = blockIdx.y * BM;
    const int bn = blockIdx.x * BN;
    const int kbase = blockIdx.z * kcps * BK;
    C += (size_t)blockIdx.z * M * N;    // partial slice

    // per-lane ldmatrix addressing (byte offsets within a plane)
    const int ra = ((lane >> 3) & 1) * 8 + (lane & 7);
    const int cha = (lane >> 4) & 1;
    const int swza = (ra >> 1) & 3;
    const uint32_t a_row = (uint32_t)(warp_m * 64 + ra) * 64;
    const uint32_t ak0 = ((cha ^ swza) << 4);
    const uint32_t ak1 = (((2 + cha) ^ swza) << 4);

    const int rb = ((lane >> 4) & 1) * 8 + (lane & 7);
    const int chb = (lane >> 3) & 1;
    const int swzb = (rb >> 1) & 3;
    const uint32_t b_row = (uint32_t)(warp_n * 32 + rb) * 64;
    const uint32_t bk0 = ((chb ^ swzb) << 4);
    const uint32_t bk1 = (((2 + chb) ^ swzb) << 4);

    float acc[4][4][4];
#pragma unroll
    for (int mt = 0; mt < 4; mt++)
#pragma unroll
        for (int nt = 0; nt < 4; nt++)
#pragma unroll
            for (int e = 0; e < 4; e++) acc[mt][nt][e] = 0.f;

    load_stage(Ahi, Alo, Whi, Wlo, M, K, bm, bn, kbase, sbase, tid);
    asm volatile("cp.async.commit_group;\n");
    if (1 < kcps)
        load_stage(Ahi, Alo, Whi, Wlo, M, K, bm, bn, kbase + BK,
                   sbase + STAGE_B, tid);
    asm volatile("cp.async.commit_group;\n");

// load all 8 B-fragment LDSMs for one ks into buffers (bhX, blX)
#define LDB_ALL(bhX, blX, bkk)                                                \
    {                                                                         \
        _Pragma("unroll") for (int q = 0; q < 2; q++) {                       \
            uint32_t ad = pBhi + b_row + q * 1024 + (bkk);                    \
            LDM4(bhX[2 * q][0], bhX[2 * q][1], bhX[2 * q + 1][0],             \
                 bhX[2 * q + 1][1], ad);                                      \
            ad = pBlo + b_row + q * 1024 + (bkk);                             \
            LDM4(blX[2 * q][0], blX[2 * q][1], blX[2 * q + 1][0],             \
                 blX[2 * q + 1][1], ad);                                      \
        }                                                                     \
    }
// load A hi/lo fragments for row-tile mt into buffer slot s
#define LDA_PAIR(s, mt, akk)                                                  \
    {                                                                         \
        uint32_t ad = pAhi + a_row + (mt) * 1024 + (akk);                     \
        LDM4(ahi[s][0], ahi[s][1], ahi[s][2], ahi[s][3], ad);                 \
        ad = pAlo + a_row + (mt) * 1024 + (akk);                              \
        LDM4(alo[s][0], alo[s][1], alo[s][2], alo[s][3], ad);                 \
    }
// interleaved pair: chain distance 8; per-acc term order fixed
// (hi*bhi, hi*blo, lo*bhi)
#define PAIR_MMA(m0, m1, bhX, blX)                                            \
    {                                                                         \
        _Pragma("unroll") for (int nt = 0; nt < 4; nt++)                      \
            MMA_BF16(acc[m0][nt], ahi[0], bhX[nt]);                           \
        _Pragma("unroll") for (int nt = 0; nt < 4; nt++)                      \
            MMA_BF16(acc[m1][nt], ahi[1], bhX[nt]);                           \
        _Pragma("unroll") for (int nt = 0; nt < 4; nt++)                      \
            MMA_BF16(acc[m0][nt], ahi[0], blX[nt]);                           \
        _Pragma("unroll") for (int nt = 0; nt < 4; nt++)                      \
            MMA_BF16(acc[m1][nt], ahi[1], blX[nt]);                           \
        _Pragma("unroll") for (int nt = 0; nt < 4; nt++)                      \
            MMA_BF16(acc[m0][nt], alo[0], bhX[nt]);                           \
        _Pragma("unroll") for (int nt = 0; nt < 4; nt++)                      \
            MMA_BF16(acc[m1][nt], alo[1], bhX[nt]);                           \
    }

    for (int it = 0; it < kcps; it++) {
        asm volatile("cp.async.wait_group 1;\n");
        __syncthreads();

        const uint32_t sb = sbase + (it % NSTG) * STAGE_B;
        const uint32_t pAhi = sb;
        const uint32_t pAlo = sb + PLANE_B;
        const uint32_t pBhi = sb + 2 * PLANE_B;
        const uint32_t pBlo = sb + 3 * PLANE_B;

        uint32_t bh0[4][2], bl0[4][2], bh1[4][2], bl1[4][2];
        uint32_t ahi[2][4], alo[2][4];

        // ---- ks = 0 ----
        LDB_ALL(bh0, bl0, bk0)
        LDA_PAIR(0, 0, ak0)
        LDA_PAIR(1, 1, ak0)
        PAIR_MMA(0, 1, bh0, bl0)
        // gmem prefetch overlapped with tensor work; commit exactly once/iter
        if (it + 2 < kcps)
            load_stage(Ahi, Alo, Whi, Wlo, M, K, bm, bn, kbase + (it + 2) * BK,
                       sbase + ((it + 2) % NSTG) * STAGE_B, tid);
        asm volatile("cp.async.commit_group;\n");
        LDA_PAIR(0, 2, ak0)
        LDA_PAIR(1, 3, ak0)
        LDB_ALL(bh1, bl1, bk1)          // ks=1 B frags under ks=0 compute
        PAIR_MMA(2, 3, bh0, bl0)

        // ---- ks = 1 ----
        LDA_PAIR(0, 0, ak1)
        LDA_PAIR(1, 1, ak1)
        PAIR_MMA(0, 1, bh1, bl1)
        LDA_PAIR(0, 2, ak1)
        LDA_PAIR(1, 3, ak1)
        PAIR_MMA(2, 3, bh1, bl1)
    }

    const int gid = lane >> 2;
    const int tig = lane & 3;
#pragma unroll
    for (int mt = 0; mt < 4; mt++) {
        int row0 = bm + warp_m * 64 + mt * 16 + gid;
        int row1 = row0 + 8;
#pragma unroll
        for (int nt = 0; nt < 4; nt++) {
            int col = bn + warp_n * 32 + nt * 8 + tig * 2;
            if (row0 < M)
                *(float2*)&C[(size_t)row0 * N + col] =
                    make_float2(acc[mt][nt][0], acc[mt][nt][1]);
            if (row1 < M)
                *(float2*)&C[(size_t)row1 * N + col] =
                    make_float2(acc[mt][nt][2], acc[mt][nt][3]);
        }
    }
}

// ---------------- elementwise gate kernels (float4 vectorized) ---------------
static __device__ __forceinline__ float sigmoidf_(float x) {
    return 1.f / (1.f + expf(-x));
}
static __device__ __forceinline__ void split_store(bf16* hhi, bf16* hlo,
                                                   int i4, float4 h) {
    bf16 h0 = __float2bfloat16(h.x), h1 = __float2bfloat16(h.y);
    bf16 h2 = __float2bfloat16(h.z), h3 = __float2bfloat16(h.w);
    ((__nv_bfloat162*)hhi)[i4 * 2]     = __nv_bfloat162(h0, h1);
    ((__nv_bfloat162*)hhi)[i4 * 2 + 1] = __nv_bfloat162(h2, h3);
    ((__nv_bfloat162*)hlo)[i4 * 2] = __nv_bfloat162(
        __float2bfloat16(h.x - __bfloat162float(h0)),
        __float2bfloat16(h.y - __bfloat162float(h1)));
    ((__nv_bfloat162*)hlo)[i4 * 2 + 1] = __nv_bfloat162(
        __float2bfloat16(h.z - __bfloat162float(h2)),
        __float2bfloat16(h.w - __bfloat162float(h3)));
}

__global__ void leaf_eltwise(const float* __restrict__ g,
                             const float* __restrict__ b,
                             float* __restrict__ c,
                             bf16* __restrict__ hhi, bf16* __restrict__ hlo,
                             int rows) {
    int i4 = blockIdx.x * blockDim.x + threadIdx.x;
    if (i4 >= rows * (MEMD / 4)) return;
    int row = i4 / (MEMD / 4);
    int m = (i4 - row * (MEMD / 4)) * 4;
    const float* gr = g + (size_t)row * 3 * MEMD;
    float4 gi = *(const float4*)&gr[m];
    float4 go = *(const float4*)&gr[MEMD + m];
    float4 gu = *(const float4*)&gr[2 * MEMD + m];
    float4 bi = *(const float4*)&b[MEMD + m];
    float4 bo = *(const float4*)&b[2 * MEMD + m];
    float4 bu = *(const float4*)&b[3 * MEMD + m];
    float4 cc, hh;
#define LEAF1(X)                                                              \
    {                                                                         \
        float iv = sigmoidf_(gi.X + bi.X), ov = sigmoidf_(go.X + bo.X);       \
        float uv = tanhf(gu.X + bu.X);                                        \
        cc.X = iv * uv; hh.X = ov * tanhf(cc.X);                              \
    }
    LEAF1(x) LEAF1(y) LEAF1(z) LEAF1(w)
#undef LEAF1
    ((float4*)c)[i4] = cc;
    split_store(hhi, hlo, i4, hh);
}

__global__ void node_eltwise(const float* __restrict__ g,
                             const float* __restrict__ b,
                             const float* __restrict__ c_prev,
                             float* __restrict__ c,
                             bf16* __restrict__ hhi, bf16* __restrict__ hlo,
                             float* __restrict__ hroot, int rows, int nsl) {
    int i4 = blockIdx.x * blockDim.x + threadIdx.x;
    if (i4 >= rows * (MEMD / 4)) return;
    int row = i4 / (MEMD / 4);
    int m = (i4 - row * (MEMD / 4)) * 4;
    const size_t sstride = (size_t)rows * 5 * MEMD;
    const float* gr = g + (size_t)row * 5 * MEMD;
    float4 gi = *(const float4*)&gr[m];
    float4 go = *(const float4*)&gr[MEMD + m];
    float4 gu = *(const float4*)&gr[2 * MEMD + m];
    float4 gfl = *(const float4*)&gr[3 * MEMD + m];
    float4 gfr = *(const float4*)&gr[4 * MEMD + m];
    for (int s = 1; s < nsl; s++) {
        const float* gs = gr + s * sstride;
        float4 t;
        t = *(const float4*)&gs[m];
        gi.x += t.x; gi.y += t.y; gi.z += t.z; gi.w += t.w;
        t = *(const float4*)&gs[MEMD + m];
        go.x += t.x; go.y += t.y; go.z += t.z; go.w += t.w;
        t = *(const float4*)&gs[2 * MEMD + m];
        gu.x += t.x; gu.y += t.y; gu.z += t.z; gu.w += t.w;
        t = *(const float4*)&gs[3 * MEMD + m];
        gfl.x += t.x; gfl.y += t.y; gfl.z += t.z; gfl.w += t.w;
        t = *(const float4*)&gs[4 * MEMD + m];
        gfr.x += t.x; gfr.y += t.y; gfr.z += t.z; gfr.w += t.w;
    }
    const float* cpr = c_prev + (size_t)row * 2 * MEMD;
    float4 bi = *(const float4*)&b[MEMD + m];
    float4 bo = *(const float4*)&b[2 * MEMD + m];
    float4 bu = *(const float4*)&b[3 * MEMD + m];
    float4 bf = *(const float4*)&b[m];
    float4 cl = *(const float4*)&cpr[m];
    float4 cr = *(const float4*)&cpr[MEMD + m];
    float4 cc, hh;
#define NODE1(X)                                                              \
    {                                                                         \
        float iv = sigmoidf_(gi.X + bi.X), ov = sigmoidf_(go.X + bo.X);       \
        float uv = tanhf(gu.X + bu.X);                                        \
        float fl = sigmoidf_(gfl.X + bf.X), fr = sigmoidf_(gfr.X + bf.X);     \
        cc.X = fmaf(iv, uv, fmaf(fl, cl.X, fr * cr.X));                       \
        hh.X = ov * tanhf(cc.X);                                              \
    }
    NODE1(x) NODE1(y) NODE1(z) NODE1(w)
#undef NODE1
    ((float4*)c)[i4] = cc;
    if (hroot)
        ((float4*)hroot)[i4] = hh;
    else
        split_store(hhi, hlo, i4, hh);
}

// ---------------- launch -----------------------------------------------------
extern "C" void kernel_launch(void* const* d_in, const int* in_sizes, int n_in,
                              void* d_out, int out_size) {
    const float* inputs  = (const float*)d_in[0];
    const float* w_fioux = (const float*)d_in[1];
    const float* b       = (const float*)d_in[2];
    const float* w_iouh  = (const float*)d_in[3];
    const float* w_fh    = (const float*)d_in[4];
    float* out = (float*)d_out;

    float *scr, *c0, *c1;
    bf16 *h0hi, *h0lo, *h1hi, *h1lo, *xhi, *xlo, *wxhi, *wxlo, *wchi, *wclo;
    cudaGetSymbolAddress((void**)&scr, g_scr);
    cudaGetSymbolAddress((void**)&c0, g_c0);
    cudaGetSymbolAddress((void**)&c1, g_c1);
    cudaGetSymbolAddress((void**)&h0hi, g_h0hi);
    cudaGetSymbolAddress((void**)&h0lo, g_h0lo);
    cudaGetSymbolAddress((void**)&h1hi, g_h1hi);
    cudaGetSymbolAddress((void**)&h1lo, g_h1lo);
    cudaGetSymbolAddress((void**)&xhi, g_xhi);
    cudaGetSymbolAddress((void**)&xlo, g_xlo);
    cudaGetSymbolAddress((void**)&wxhi, g_wxhi);
    cudaGetSymbolAddress((void**)&wxlo, g_wxlo);
    cudaGetSymbolAddress((void**)&wchi, g_wchi);
    cudaGetSymbolAddress((void**)&wclo, g_wclo);

    cudaFuncSetAttribute(gemm_split, cudaFuncAttributeMaxDynamicSharedMemorySize,
                         SMEM_DYN);

    const int rowsL = BB * NL;  // 16384

    {
        int n0 = rowsL * INDIM / 4;
        int n1 = 3 * MEMD * INDIM / 4;
        int n2 = 3 * MEMD * 2 * MEMD / 4;
        int n3 = 2 * MEMD * 2 * MEMD / 4;
        size_t off = (size_t)3 * MEMD * 2 * MEMD;
        int tot = n0 + n1 + n2 + n3;
        split_all<<<(tot + 255) / 256, 256>>>(
            inputs, xhi, xlo, n0,
            w_fioux + (size_t)MEMD * INDIM, wxhi, wxlo, n1,
            w_iouh, wchi, wclo, n2,
            w_fh, wchi + off, wclo + off, n3);
    }

    gemm_split<<<dim3(3 * MEMD / BN, rowsL / BM, 1), 256, SMEM_DYN>>>(
        xhi, xlo, wxhi, wxlo, scr, rowsL, 3 * MEMD, INDIM, INDIM / BK);
    leaf_eltwise<<<(rowsL * MEMD / 4 + 255) / 256, 256>>>(scr, b, c0, h0hi,
                                                          h0lo, rowsL);

    float *cp = c0, *cn = c1;
    bf16 *hpi = h0hi, *hpl = h0lo, *hni = h1hi, *hnl = h1lo;
    for (int n = NL / 2; n >= 1; n >>= 1) {
        int rows = BB * n;
        int ks = rows >= 1024 ? 1
               : rows == 512 ? 2
               : rows == 256 ? 4
               : rows == 128 ? 8 : 16;
        int kcps = (2 * MEMD / BK) / ks;   // 64 / ks
        int gy = (rows + BM - 1) / BM;
        gemm_split<<<dim3(5 * MEMD / BN, gy, ks), 256, SMEM_DYN>>>(
            hpi, hpl, wchi, wclo, scr, rows, 5 * MEMD, 2 * MEMD, kcps);
        node_eltwise<<<(rows * MEMD / 4 + 255) / 256, 256>>>(
            scr, b, cp, cn, hni, hnl, (n == 1) ? out : (float*)nullptr, rows, ks);
        float* tc = cp; cp = cn; cn = tc;
        bf16* t;
        t = hpi; hpi = hni; hni = t;
        t = hpl; hpl = hnl; hnl = t;
    }
}